// round 17
// baseline (speedup 1.0000x reference)
#include <cuda_runtime.h>
#include <cuda_bf16.h>

// AllReduce(sum over tp=8) + residual add + RMSNorm, fused single pass.
// R17: probe 256-bit memory ops (sm_100a+: ld/st.global.v8.f32 ->
// LDG.E.256 / STG.E.256). Same mandatory traffic, same 9 loads/thread, but
// each warp-load touches 8 full 128B lines -> half the L1tex wavefronts and
// LSU slots per byte vs the v4 kernel (R9). 512 threads x 8 floats = 4096
// row; __launch_bounds__(512,4) keeps 64 warps/SM like R9. Everything else
// identical to R9 (streaming policy, hidden-store pre-barrier, single
// barrier, redundant final reduce, weight post-barrier).

constexpr int TOKENS = 4096;
constexpr int HIDDEN = 4096;
constexpr int TP     = 8;
constexpr int NTHREADS = 512;
constexpr int NWARPS  = NTHREADS / 32;    // 16
constexpr float EPS = 1e-6f;

// 256-bit streaming global load: 8 consecutive f32.
__device__ __forceinline__ void ldg_cs_v8(const float* __restrict__ p, float* r)
{
    asm volatile(
        "ld.global.cs.v8.f32 {%0,%1,%2,%3,%4,%5,%6,%7}, [%8];"
        : "=f"(r[0]), "=f"(r[1]), "=f"(r[2]), "=f"(r[3]),
          "=f"(r[4]), "=f"(r[5]), "=f"(r[6]), "=f"(r[7])
        : "l"(p));
}

// 256-bit streaming global store: 8 consecutive f32.
__device__ __forceinline__ void stg_cs_v8(float* __restrict__ p, const float* r)
{
    asm volatile(
        "st.global.cs.v8.f32 [%0], {%1,%2,%3,%4,%5,%6,%7,%8};"
        :: "l"(p),
           "f"(r[0]), "f"(r[1]), "f"(r[2]), "f"(r[3]),
           "f"(r[4]), "f"(r[5]), "f"(r[6]), "f"(r[7])
        : "memory");
}

__global__ __launch_bounds__(NTHREADS, 4) void allreduce_rmsnorm_kernel(
    const float* __restrict__ input,     // [TP, TOKENS, HIDDEN]
    const float* __restrict__ residual,  // [TOKENS, HIDDEN]
    const float* __restrict__ weight,    // [HIDDEN]
    float* __restrict__ out_norm,        // [TOKENS, HIDDEN]
    float* __restrict__ out_hidden)      // [TOKENS, HIDDEN]
{
    const int token = blockIdx.x;
    const int tid   = threadIdx.x;
    const int lane  = tid & 31;
    const int wid   = tid >> 5;

    const size_t row_off   = (size_t)token * HIDDEN;
    const size_t tp_stride = (size_t)TOKENS * HIDDEN;
    const int    elem      = tid * 8;     // 8 consecutive floats per thread

    const float* __restrict__ in_row = input + row_off + elem;

    // Single accumulation stream: 9 independent 256-bit streaming loads.
    float a[8];
    ldg_cs_v8(residual + row_off + elem, a);

    #pragma unroll
    for (int t = 0; t < TP; t++) {
        float v[8];
        ldg_cs_v8(in_row + (size_t)t * tp_stride, v);
        #pragma unroll
        for (int i = 0; i < 8; i++) a[i] += v[i];
    }

    float ss = 0.0f;
    #pragma unroll
    for (int i = 0; i < 8; i++) ss = fmaf(a[i], a[i], ss);

    // Residual-stream output does not depend on rstd: store before the
    // barrier so DRAM stays busy through the reduce window.
    stg_cs_v8(out_hidden + row_off + elem, a);

    // Warp reduce -> smem -> single barrier -> redundant per-thread finish.
    #pragma unroll
    for (int off = 16; off > 0; off >>= 1)
        ss += __shfl_xor_sync(0xFFFFFFFFu, ss, off);

    __shared__ float warp_ss[NWARPS];
    if (lane == 0) warp_ss[wid] = ss;
    __syncthreads();

    float tot = 0.0f;
    #pragma unroll
    for (int w = 0; w < NWARPS; w++)
        tot += warp_ss[w];
    const float rstd = rsqrtf(tot * (1.0f / (float)HIDDEN) + EPS);

    // Normalized output; weight is 16KB, reused by all CTAs -> L2-cached.
    const float4 w0 = __ldg((const float4*)(weight + elem));
    const float4 w1 = __ldg((const float4*)(weight + elem + 4));
    float n[8];
    n[0] = a[0] * rstd * w0.x; n[1] = a[1] * rstd * w0.y;
    n[2] = a[2] * rstd * w0.z; n[3] = a[3] * rstd * w0.w;
    n[4] = a[4] * rstd * w1.x; n[5] = a[5] * rstd * w1.y;
    n[6] = a[6] * rstd * w1.z; n[7] = a[7] * rstd * w1.w;
    stg_cs_v8(out_norm + row_off + elem, n);
}

extern "C" void kernel_launch(void* const* d_in, const int* in_sizes, int n_in,
                              void* d_out, int out_size)
{
    const float* input    = (const float*)d_in[0];
    const float* residual = (const float*)d_in[1];
    const float* weight   = (const float*)d_in[2];

    float* out_norm   = (float*)d_out;
    float* out_hidden = (float*)d_out + (size_t)TOKENS * HIDDEN;

    allreduce_rmsnorm_kernel<<<TOKENS, NTHREADS>>>(
        input, residual, weight, out_norm, out_hidden);
}